// round 14
// baseline (speedup 1.0000x reference)
#include <cuda_runtime.h>
#include <cuda_fp16.h>
#include <mma.h>

using namespace nvcuda;

#define B_    32
#define S_    4096
#define D_    1024
#define H_    512
#define BM    64
#define BKC   64
#define NCHP  16               // chunks per tile
#define NTILES 2048            // (S_/BM) * B_
#define GRIDP 148
#define APAD  72
#define BPADB 520
#define NTHREADS 512

__device__ __align__(16) __half g_W1h[D_ * H_];
__device__ float g_pacc[(size_t)NTILES * D_];   // per-tile weighted x partial
__device__ float g_pmz[NTILES * 2];             // per-tile (max, Z)

struct alignas(8) H4 { __half2 a, b; };

__device__ __forceinline__ void cp_async16(void* smem, const void* gmem) {
    unsigned s = (unsigned)__cvta_generic_to_shared(smem);
    asm volatile("cp.async.cg.shared.global [%0], [%1], 16;\n" :: "r"(s), "l"(gmem));
}
__device__ __forceinline__ void cp_async_commit() {
    asm volatile("cp.async.commit_group;\n");
}
__device__ __forceinline__ void cp_async_wait_all() {
    asm volatile("cp.async.wait_group 0;\n");
}

// ---------------- K0: W1 fp32 -> fp16 (512 CTAs, 2 float4/thread) ----------
__global__ void convert_w1_kernel(const float* __restrict__ W1) {
    const int base = blockIdx.x * (blockDim.x * 2) + threadIdx.x;
    const float4 v0 = ((const float4*)W1)[base];
    const float4 v1 = ((const float4*)W1)[base + 256];
    H4 o0, o1;
    o0.a = __floats2half2_rn(v0.x, v0.y);
    o0.b = __floats2half2_rn(v0.z, v0.w);
    o1.a = __floats2half2_rn(v1.x, v1.y);
    o1.b = __floats2half2_rn(v1.z, v1.w);
    ((H4*)g_W1h)[base] = o0;
    ((H4*)g_W1h)[base + 256] = o1;
}

// ---------------- K1: persistent fused scores + online-softmax partials ----
// For each 64-row tile: scores = w2 . ReLU((x*prev)@W1 + b1)  (b2 cancels in
// softmax), then m_t = max, p = exp(score-m_t), Z_t = sum p, and
// acc_t[d] = sum_r p_r * x[r,d]  (x re-read is L2-resident).
__global__ void __launch_bounds__(NTHREADS, 1)
scores_kernel(const float* __restrict__ x, const float* __restrict__ prev,
              const float* __restrict__ b1, const float* __restrict__ w2) {
    extern __shared__ char smem_raw[];
    __half* Ah = (__half*)smem_raw;                    // 2 * BM * APAD halves
    __half* Bs = Ah + 2 * BM * APAD;                   // 2 * BKC * BPADB halves
    float*  psbuf = (float*)(Bs + 2 * BKC * BPADB);    // D_ floats
    float*  b1s = psbuf + D_;                          // H_
    float*  w2s = b1s + H_;                            // H_
    float*  scoreBuf = w2s + H_;                       // BM
    float*  pbuf = scoreBuf + BM;                      // BM
    float*  redsm = pbuf + BM;                         // 4
    float*  stage = redsm + 4;                         // 16 warps * 320 floats

    const int tid  = threadIdx.x;
    const int warp = tid >> 5;
    const int lane = tid & 31;
    const int bid  = blockIdx.x;
    const int arow0 = tid >> 4;     // 0..31
    const int c4    = tid & 15;     // 0..15
    const int wm = warp >> 3;       // 0..1
    const int wn = warp & 7;        // 0..7

    const int nloc = (NTILES - bid + GRIDP - 1) / GRIDP;
    const int G = nloc * NCHP;

    for (int i = tid; i < H_; i += NTHREADS) { b1s[i] = b1[i]; w2s[i] = w2[i]; }
    {   // prev for tile 0
        const int b0 = bid >> 6;
        for (int i = tid; i < D_; i += NTHREADS) psbuf[i] = prev[b0 * D_ + i];
    }
    if (tid < BM) scoreBuf[tid] = 0.f;
    __syncthreads();

    // ---- prologue: stage chunk 0 of tile 0 into buffer 0 ----
    {
        const size_t row0 = (size_t)(bid >> 6) * S_ + (size_t)(bid & 63) * BM;
        const float* xb0 = x + row0 * D_;
        #pragma unroll
        for (int j = 0; j < 2; ++j) {
            const int row = arow0 + j * 32;
            float4 v = *(const float4*)(xb0 + (size_t)row * D_ + c4 * 4);
            float4 p = *(const float4*)(psbuf + c4 * 4);
            v.x *= p.x; v.y *= p.y; v.z *= p.z; v.w *= p.w;
            H4 cv;
            cv.a = __floats2half2_rn(v.x, v.y);
            cv.b = __floats2half2_rn(v.z, v.w);
            *(H4*)(Ah + (size_t)row * APAD + c4 * 4) = cv;
        }
        #pragma unroll
        for (int j = 0; j < 8; ++j) {
            const int u = tid + j * NTHREADS;
            const int row = u >> 6, c16 = u & 63;
            cp_async16(Bs + (size_t)row * BPADB + c16 * 8,
                       g_W1h + (size_t)row * H_ + c16 * 8);
        }
        cp_async_commit();
    }

    wmma::fragment<wmma::matrix_a, 16, 16, 16, __half, wmma::row_major> af[2];
    wmma::fragment<wmma::matrix_b, 16, 16, 16, __half, wmma::row_major> bf;
    wmma::fragment<wmma::accumulator, 16, 16, 16, float> acc[2][4];
    #pragma unroll
    for (int mi = 0; mi < 2; ++mi)
        #pragma unroll
        for (int ni = 0; ni < 4; ++ni)
            wmma::fill_fragment(acc[mi][ni], 0.f);

    for (int g = 0; g < G; ++g) {
        const int  c    = g & 15;
        const int  tcur = bid + (g >> 4) * GRIDP;
        const bool last = (g + 1 == G);
        const int  cn   = (g + 1) & 15;
        const int  tnx  = bid + ((g + 1) >> 4) * GRIDP;
        const int  kcn  = cn * BKC;
        const size_t rownx = (size_t)(tnx >> 6) * S_ + (size_t)(tnx & 63) * BM;

        // ---- prefetch phase (hide LDG latency under wait+mma) ----
        float4 pref0, pref1, psA, psC;
        if (!last) {
            const float* xbn = x + rownx * D_;
            pref0 = *(const float4*)(xbn + (size_t)arow0 * D_ + kcn + c4 * 4);
            pref1 = *(const float4*)(xbn + (size_t)(arow0 + 32) * D_ + kcn + c4 * 4);
            if (cn == 0) {
                const float* pnx = prev + (size_t)(tnx >> 6) * D_;
                psA = *(const float4*)(pnx + c4 * 4);
                if (tid < 256) psC = ((const float4*)pnx)[tid];
            }
        }

        cp_async_wait_all();
        __syncthreads();        // buffers for chunk g fully staged & visible

        // ---- stage chunk g+1 into the other buffer (overlaps MMA on g) ----
        if (!last) {
            const int nb = (g + 1) & 1;
            if (cn == 0 && tid < 256) ((float4*)psbuf)[tid] = psC;
            const float4 psv = (cn == 0) ? psA
                             : *(const float4*)(psbuf + kcn + c4 * 4);
            {
                float4 v = pref0; const int row = arow0;
                v.x *= psv.x; v.y *= psv.y; v.z *= psv.z; v.w *= psv.w;
                H4 cv;
                cv.a = __floats2half2_rn(v.x, v.y);
                cv.b = __floats2half2_rn(v.z, v.w);
                *(H4*)(Ah + (size_t)nb * BM * APAD + (size_t)row * APAD + c4 * 4) = cv;
            }
            {
                float4 v = pref1; const int row = arow0 + 32;
                v.x *= psv.x; v.y *= psv.y; v.z *= psv.z; v.w *= psv.w;
                H4 cv;
                cv.a = __floats2half2_rn(v.x, v.y);
                cv.b = __floats2half2_rn(v.z, v.w);
                *(H4*)(Ah + (size_t)nb * BM * APAD + (size_t)row * APAD + c4 * 4) = cv;
            }
            #pragma unroll
            for (int j = 0; j < 8; ++j) {
                const int u = tid + j * NTHREADS;
                const int row = u >> 6, c16 = u & 63;
                cp_async16(Bs + (size_t)nb * BKC * BPADB + (size_t)row * BPADB + c16 * 8,
                           g_W1h + (size_t)(kcn + row) * H_ + c16 * 8);
            }
            cp_async_commit();
        }

        // ---- MMA on buffer g&1 ----
        const __half* Ab = Ah + (size_t)(g & 1) * BM * APAD;
        const __half* Bb = Bs + (size_t)(g & 1) * BKC * BPADB;
        #pragma unroll
        for (int kt = 0; kt < BKC; kt += 16) {
            wmma::load_matrix_sync(af[0], Ab + (size_t)(wm * 32 +  0) * APAD + kt, APAD);
            wmma::load_matrix_sync(af[1], Ab + (size_t)(wm * 32 + 16) * APAD + kt, APAD);
            #pragma unroll
            for (int ni = 0; ni < 4; ++ni) {
                wmma::load_matrix_sync(bf, Bb + (size_t)kt * BPADB + wn * 64 + ni * 16, BPADB);
                wmma::mma_sync(acc[0][ni], af[0], bf, acc[0][ni]);
                wmma::mma_sync(acc[1][ni], af[1], bf, acc[1][ni]);
            }
        }

        // ---- per-tile epilogue: scores -> softmax partial -> weighted x ----
        if (c == 15) {
            float* st = stage + warp * 320;
            #pragma unroll
            for (int mi = 0; mi < 2; ++mi) {
                float rowsum = 0.f;
                #pragma unroll
                for (int ni = 0; ni < 4; ++ni) {
                    wmma::store_matrix_sync(st, acc[mi][ni], 20, wmma::mem_row_major);
                    __syncwarp();
                    const int rr = lane >> 1;
                    const int cc0 = (lane & 1) * 8;
                    const int hb = wn * 64 + ni * 16;
                    float sum = 0.f;
                    #pragma unroll
                    for (int j = 0; j < 8; ++j) {
                        const int cc = cc0 + j;
                        float v = st[rr * 20 + cc] + b1s[hb + cc];
                        sum += fmaxf(v, 0.f) * w2s[hb + cc];
                    }
                    rowsum += sum;
                    __syncwarp();
                }
                rowsum += __shfl_xor_sync(0xffffffffu, rowsum, 1);
                if ((lane & 1) == 0)
                    atomicAdd(&scoreBuf[wm * 32 + mi * 16 + (lane >> 1)], rowsum);
            }
            __syncthreads();

            // tile max / Z (warps 0-1 hold the 64 scores)
            const float sc = (tid < BM) ? scoreBuf[tid] : -1e30f;
            float m = sc;
            #pragma unroll
            for (int o = 16; o > 0; o >>= 1)
                m = fmaxf(m, __shfl_xor_sync(0xffffffffu, m, o));
            if (tid < BM && lane == 0) redsm[warp] = m;
            __syncthreads();
            const float mt = fmaxf(redsm[0], redsm[1]);
            float p = 0.f;
            if (tid < BM) { p = __expf(sc - mt); pbuf[tid] = p; }
            float zz = p;
            #pragma unroll
            for (int o = 16; o > 0; o >>= 1)
                zz += __shfl_xor_sync(0xffffffffu, zz, o);
            if (tid < BM && lane == 0) redsm[2 + warp] = zz;
            __syncthreads();
            if (tid == 0) {
                g_pmz[tcur * 2]     = mt;
                g_pmz[tcur * 2 + 1] = redsm[2] + redsm[3];
            }

            // weighted x accumulation over this tile (L2-resident re-read)
            const size_t rowcur = (size_t)(tcur >> 6) * S_ + (size_t)(tcur & 63) * BM;
            const float2* xp = (const float2*)(x + rowcur * D_) + tid;
            float2 a = make_float2(0.f, 0.f);
            #pragma unroll 8
            for (int r = 0; r < BM; ++r) {
                const float pr = pbuf[r];
                const float2 v = xp[(size_t)r * (D_ / 2)];
                a.x += pr * v.x; a.y += pr * v.y;
            }
            ((float2*)(g_pacc + (size_t)tcur * D_))[tid] = a;

            if (tid < BM) scoreBuf[tid] = 0.f;
            #pragma unroll
            for (int mi = 0; mi < 2; ++mi)
                #pragma unroll
                for (int ni = 0; ni < 4; ++ni)
                    wmma::fill_fragment(acc[mi][ni], 0.f);
            // next tile's atomics ordered after reset by next iteration's barrier
        }
    }
}

// ---------------- K2: finalize — merge 64 tile-partials per batch ----------
// grid (B_, 8): block (b,q) owns float2 columns [q*64, q*64+64).
// col = tid & 63, tile-group = tid >> 6 (8 tiles each); merged via smem.
__global__ void __launch_bounds__(512)
finalize_kernel(float* __restrict__ out) {
    __shared__ float coef[64];
    __shared__ float red[4];
    __shared__ float2 part[512];
    const int b = blockIdx.x, q = blockIdx.y;
    const int tid = threadIdx.x;
    const int lane = tid & 31, warp = tid >> 5;

    float m_t = -1e30f, z_t = 0.f;
    if (tid < 64) {
        m_t = g_pmz[(b * 64 + tid) * 2];
        z_t = g_pmz[(b * 64 + tid) * 2 + 1];
    }
    float m = m_t;
    #pragma unroll
    for (int o = 16; o > 0; o >>= 1)
        m = fmaxf(m, __shfl_xor_sync(0xffffffffu, m, o));
    if (tid < 64 && lane == 0) red[warp] = m;
    __syncthreads();
    const float M = fmaxf(red[0], red[1]);
    float cc = 0.f;
    if (tid < 64) { cc = __expf(m_t - M); coef[tid] = cc; }
    float zz = z_t * cc;
    #pragma unroll
    for (int o = 16; o > 0; o >>= 1)
        zz += __shfl_xor_sync(0xffffffffu, zz, o);
    if (tid < 64 && lane == 0) red[2 + warp] = zz;
    __syncthreads();
    const float inv = 1.f / (red[2] + red[3]);

    const int col = tid & 63;           // float2 column within slice
    const int tg  = tid >> 6;           // tile group 0..7
    const float2* pa = (const float2*)(g_pacc + (size_t)b * 64 * D_)
                     + (size_t)q * 64 + col;
    float2 a = make_float2(0.f, 0.f);
    #pragma unroll
    for (int t = 0; t < 8; ++t) {
        const int tt = tg * 8 + t;
        const float c = coef[tt];
        const float2 v = pa[(size_t)tt * (D_ / 2)];
        a.x += c * v.x; a.y += c * v.y;
    }
    part[tid] = a;
    __syncthreads();
    if (tid < 64) {
        float2 s = part[tid];
        #pragma unroll
        for (int t = 1; t < 8; ++t) {
            const float2 v = part[t * 64 + tid];
            s.x += v.x; s.y += v.y;
        }
        s.x *= inv; s.y *= inv;
        ((float2*)(out + b * D_))[q * 64 + tid] = s;
    }
}

extern "C" void kernel_launch(void* const* d_in, const int* in_sizes, int n_in,
                              void* d_out, int out_size) {
    const float* x    = (const float*)d_in[0];
    const float* prev = (const float*)d_in[1];
    const float* W1   = (const float*)d_in[2];
    const float* b1   = (const float*)d_in[3];
    const float* w2   = (const float*)d_in[4];
    float* out = (float*)d_out;

    const size_t smem = (size_t)2 * BM * APAD * 2      // Ah
                      + (size_t)2 * BKC * BPADB * 2    // Bs
                      + (size_t)D_ * 4                 // psbuf
                      + (size_t)H_ * 4 * 2             // b1s + w2s
                      + (size_t)BM * 4 * 2             // scoreBuf + pbuf
                      + 4 * 4                          // redsm
                      + (size_t)16 * 320 * 4;          // stage
    cudaFuncSetAttribute(scores_kernel, cudaFuncAttributeMaxDynamicSharedMemorySize, (int)smem);

    // 131072 float4 slots; 256 blocks * 256 threads * 2 each
    convert_w1_kernel<<<256, 256>>>(W1);
    scores_kernel<<<GRIDP, NTHREADS, smem>>>(x, prev, b1, w2);
    finalize_kernel<<<dim3(B_, 8), 512>>>(out);
}

// round 15
// speedup vs baseline: 1.0035x; 1.0035x over previous
#include <cuda_runtime.h>
#include <cuda_fp16.h>
#include <mma.h>

using namespace nvcuda;

#define B_    32
#define S_    4096
#define D_    1024
#define H_    512
#define BM    64
#define BKC   64
#define NCHP  16               // chunks per tile
#define NTILES 2048            // (S_/BM) * B_
#define GRIDP 148
#define APAD  72
#define BPADB 520
#define NTHREADS 512

__device__ __align__(16) __half g_W1h[D_ * H_];
__device__ float g_pacc[(size_t)NTILES * D_];   // per-tile weighted x partial
__device__ float g_pmz[NTILES * 2];             // per-tile (max, Z)

struct alignas(8) H4 { __half2 a, b; };

__device__ __forceinline__ void cp_async16(void* smem, const void* gmem) {
    unsigned s = (unsigned)__cvta_generic_to_shared(smem);
    asm volatile("cp.async.cg.shared.global [%0], [%1], 16;\n" :: "r"(s), "l"(gmem));
}
__device__ __forceinline__ void cp_async_commit() {
    asm volatile("cp.async.commit_group;\n");
}
__device__ __forceinline__ void cp_async_wait_all() {
    asm volatile("cp.async.wait_group 0;\n");
}

// ---------------- K0: W1 fp32 -> fp16 (grid-stride, MLP=4) ----------------
__global__ void convert_w1_kernel(const float* __restrict__ W1) {
    const int base = blockIdx.x * (blockDim.x * 4) + threadIdx.x;
    float4 v[4];
    #pragma unroll
    for (int j = 0; j < 4; ++j)
        v[j] = ((const float4*)W1)[base + j * 256];
    #pragma unroll
    for (int j = 0; j < 4; ++j) {
        H4 o;
        o.a = __floats2half2_rn(v[j].x, v[j].y);
        o.b = __floats2half2_rn(v[j].z, v[j].w);
        ((H4*)g_W1h)[base + j * 256] = o;
    }
}

// ---------------- K1: persistent fused scores + online-softmax partials ----
// For each 64-row tile: scores = w2 . ReLU((x*prev)@W1 + b1)  (b2 cancels in
// softmax), then m_t = max, p = exp(score-m_t), Z_t = sum p, and
// acc_t[d] = sum_r p_r * x[r,d]  (x re-read is L2-resident).
__global__ void __launch_bounds__(NTHREADS, 1)
scores_kernel(const float* __restrict__ x, const float* __restrict__ prev,
              const float* __restrict__ b1, const float* __restrict__ w2) {
    extern __shared__ char smem_raw[];
    __half* Ah = (__half*)smem_raw;                    // 2 * BM * APAD halves
    __half* Bs = Ah + 2 * BM * APAD;                   // 2 * BKC * BPADB halves
    float*  psbuf = (float*)(Bs + 2 * BKC * BPADB);    // D_ floats
    float*  b1s = psbuf + D_;                          // H_
    float*  w2s = b1s + H_;                            // H_
    float*  scoreBuf = w2s + H_;                       // BM
    float*  pbuf = scoreBuf + BM;                      // BM
    float*  redsm = pbuf + BM;                         // 4
    float*  stage = redsm + 4;                         // 16 warps * 320 floats

    const int tid  = threadIdx.x;
    const int warp = tid >> 5;
    const int lane = tid & 31;
    const int bid  = blockIdx.x;
    const int arow0 = tid >> 4;     // 0..31
    const int c4    = tid & 15;     // 0..15
    const int wm = warp >> 3;       // 0..1
    const int wn = warp & 7;        // 0..7

    const int nloc = (NTILES - bid + GRIDP - 1) / GRIDP;
    const int G = nloc * NCHP;

    for (int i = tid; i < H_; i += NTHREADS) { b1s[i] = b1[i]; w2s[i] = w2[i]; }
    {   // prev for tile 0
        const int b0 = bid >> 6;
        for (int i = tid; i < D_; i += NTHREADS) psbuf[i] = prev[b0 * D_ + i];
    }
    if (tid < BM) scoreBuf[tid] = 0.f;
    __syncthreads();

    // ---- prologue: stage chunk 0 of tile 0 into buffer 0 ----
    {
        const size_t row0 = (size_t)(bid >> 6) * S_ + (size_t)(bid & 63) * BM;
        const float* xb0 = x + row0 * D_;
        #pragma unroll
        for (int j = 0; j < 2; ++j) {
            const int row = arow0 + j * 32;
            float4 v = *(const float4*)(xb0 + (size_t)row * D_ + c4 * 4);
            float4 p = *(const float4*)(psbuf + c4 * 4);
            v.x *= p.x; v.y *= p.y; v.z *= p.z; v.w *= p.w;
            H4 cv;
            cv.a = __floats2half2_rn(v.x, v.y);
            cv.b = __floats2half2_rn(v.z, v.w);
            *(H4*)(Ah + (size_t)row * APAD + c4 * 4) = cv;
        }
        #pragma unroll
        for (int j = 0; j < 8; ++j) {
            const int u = tid + j * NTHREADS;
            const int row = u >> 6, c16 = u & 63;
            cp_async16(Bs + (size_t)row * BPADB + c16 * 8,
                       g_W1h + (size_t)row * H_ + c16 * 8);
        }
        cp_async_commit();
    }

    wmma::fragment<wmma::matrix_a, 16, 16, 16, __half, wmma::row_major> af[2];
    wmma::fragment<wmma::matrix_b, 16, 16, 16, __half, wmma::row_major> bf;
    wmma::fragment<wmma::accumulator, 16, 16, 16, float> acc[2][4];
    #pragma unroll
    for (int mi = 0; mi < 2; ++mi)
        #pragma unroll
        for (int ni = 0; ni < 4; ++ni)
            wmma::fill_fragment(acc[mi][ni], 0.f);

    for (int g = 0; g < G; ++g) {
        const int  c    = g & 15;
        const int  tcur = bid + (g >> 4) * GRIDP;
        const bool last = (g + 1 == G);
        const int  cn   = (g + 1) & 15;
        const int  tnx  = bid + ((g + 1) >> 4) * GRIDP;
        const int  kcn  = cn * BKC;
        const size_t rownx = (size_t)(tnx >> 6) * S_ + (size_t)(tnx & 63) * BM;

        // ---- prefetch phase (hide LDG latency under wait+mma) ----
        float4 pref0, pref1, psA, psC;
        if (!last) {
            const float* xbn = x + rownx * D_;
            pref0 = *(const float4*)(xbn + (size_t)arow0 * D_ + kcn + c4 * 4);
            pref1 = *(const float4*)(xbn + (size_t)(arow0 + 32) * D_ + kcn + c4 * 4);
            if (cn == 0) {
                const float* pnx = prev + (size_t)(tnx >> 6) * D_;
                psA = *(const float4*)(pnx + c4 * 4);
                if (tid < 256) psC = ((const float4*)pnx)[tid];
            }
        }

        cp_async_wait_all();
        __syncthreads();        // buffers for chunk g fully staged & visible

        // ---- stage chunk g+1 into the other buffer (overlaps MMA on g) ----
        if (!last) {
            const int nb = (g + 1) & 1;
            if (cn == 0 && tid < 256) ((float4*)psbuf)[tid] = psC;
            const float4 psv = (cn == 0) ? psA
                             : *(const float4*)(psbuf + kcn + c4 * 4);
            {
                float4 v = pref0; const int row = arow0;
                v.x *= psv.x; v.y *= psv.y; v.z *= psv.z; v.w *= psv.w;
                H4 cv;
                cv.a = __floats2half2_rn(v.x, v.y);
                cv.b = __floats2half2_rn(v.z, v.w);
                *(H4*)(Ah + (size_t)nb * BM * APAD + (size_t)row * APAD + c4 * 4) = cv;
            }
            {
                float4 v = pref1; const int row = arow0 + 32;
                v.x *= psv.x; v.y *= psv.y; v.z *= psv.z; v.w *= psv.w;
                H4 cv;
                cv.a = __floats2half2_rn(v.x, v.y);
                cv.b = __floats2half2_rn(v.z, v.w);
                *(H4*)(Ah + (size_t)nb * BM * APAD + (size_t)row * APAD + c4 * 4) = cv;
            }
            #pragma unroll
            for (int j = 0; j < 8; ++j) {
                const int u = tid + j * NTHREADS;
                const int row = u >> 6, c16 = u & 63;
                cp_async16(Bs + (size_t)nb * BKC * BPADB + (size_t)row * BPADB + c16 * 8,
                           g_W1h + (size_t)(kcn + row) * H_ + c16 * 8);
            }
            cp_async_commit();
        }

        // ---- MMA on buffer g&1 ----
        const __half* Ab = Ah + (size_t)(g & 1) * BM * APAD;
        const __half* Bb = Bs + (size_t)(g & 1) * BKC * BPADB;
        #pragma unroll
        for (int kt = 0; kt < BKC; kt += 16) {
            wmma::load_matrix_sync(af[0], Ab + (size_t)(wm * 32 +  0) * APAD + kt, APAD);
            wmma::load_matrix_sync(af[1], Ab + (size_t)(wm * 32 + 16) * APAD + kt, APAD);
            #pragma unroll
            for (int ni = 0; ni < 4; ++ni) {
                wmma::load_matrix_sync(bf, Bb + (size_t)kt * BPADB + wn * 64 + ni * 16, BPADB);
                wmma::mma_sync(acc[0][ni], af[0], bf, acc[0][ni]);
                wmma::mma_sync(acc[1][ni], af[1], bf, acc[1][ni]);
            }
        }

        // ---- per-tile epilogue: scores -> softmax partial -> weighted x ----
        if (c == 15) {
            float* st = stage + warp * 320;
            #pragma unroll
            for (int mi = 0; mi < 2; ++mi) {
                float rowsum = 0.f;
                #pragma unroll
                for (int ni = 0; ni < 4; ++ni) {
                    wmma::store_matrix_sync(st, acc[mi][ni], 20, wmma::mem_row_major);
                    __syncwarp();
                    const int rr = lane >> 1;
                    const int cc0 = (lane & 1) * 8;
                    const int hb = wn * 64 + ni * 16;
                    float sum = 0.f;
                    #pragma unroll
                    for (int j = 0; j < 8; ++j) {
                        const int cc = cc0 + j;
                        float v = st[rr * 20 + cc] + b1s[hb + cc];
                        sum += fmaxf(v, 0.f) * w2s[hb + cc];
                    }
                    rowsum += sum;
                    __syncwarp();
                }
                rowsum += __shfl_xor_sync(0xffffffffu, rowsum, 1);
                if ((lane & 1) == 0)
                    atomicAdd(&scoreBuf[wm * 32 + mi * 16 + (lane >> 1)], rowsum);
            }
            __syncthreads();

            // tile max / Z (warps 0-1 hold the 64 scores)
            const float sc = (tid < BM) ? scoreBuf[tid] : -1e30f;
            float m = sc;
            #pragma unroll
            for (int o = 16; o > 0; o >>= 1)
                m = fmaxf(m, __shfl_xor_sync(0xffffffffu, m, o));
            if (tid < BM && lane == 0) redsm[warp] = m;
            __syncthreads();
            const float mt = fmaxf(redsm[0], redsm[1]);
            float p = 0.f;
            if (tid < BM) { p = __expf(sc - mt); pbuf[tid] = p; }
            float zz = p;
            #pragma unroll
            for (int o = 16; o > 0; o >>= 1)
                zz += __shfl_xor_sync(0xffffffffu, zz, o);
            if (tid < BM && lane == 0) redsm[2 + warp] = zz;
            __syncthreads();
            if (tid == 0) {
                g_pmz[tcur * 2]     = mt;
                g_pmz[tcur * 2 + 1] = redsm[2] + redsm[3];
            }

            // weighted x accumulation over this tile (L2-resident re-read)
            const size_t rowcur = (size_t)(tcur >> 6) * S_ + (size_t)(tcur & 63) * BM;
            const float2* xp = (const float2*)(x + rowcur * D_) + tid;
            float2 a = make_float2(0.f, 0.f);
            #pragma unroll 8
            for (int r = 0; r < BM; ++r) {
                const float pr = pbuf[r];
                const float2 v = xp[(size_t)r * (D_ / 2)];
                a.x += pr * v.x; a.y += pr * v.y;
            }
            ((float2*)(g_pacc + (size_t)tcur * D_))[tid] = a;

            if (tid < BM) scoreBuf[tid] = 0.f;
            #pragma unroll
            for (int mi = 0; mi < 2; ++mi)
                #pragma unroll
                for (int ni = 0; ni < 4; ++ni)
                    wmma::fill_fragment(acc[mi][ni], 0.f);
            // next tile's atomics ordered after reset by next iteration's barrier
        }
    }
}

// ---------------- K2: finalize — merge 64 tile-partials per batch ----------
// grid (B_, 8): block (b,q) owns float2 columns [q*64, q*64+64).
// col = tid & 63, tile-group = tid >> 6 (8 tiles each); merged via smem.
__global__ void __launch_bounds__(512)
finalize_kernel(float* __restrict__ out) {
    __shared__ float coef[64];
    __shared__ float red[4];
    __shared__ float2 part[512];
    const int b = blockIdx.x, q = blockIdx.y;
    const int tid = threadIdx.x;
    const int lane = tid & 31, warp = tid >> 5;

    float m_t = -1e30f, z_t = 0.f;
    if (tid < 64) {
        m_t = g_pmz[(b * 64 + tid) * 2];
        z_t = g_pmz[(b * 64 + tid) * 2 + 1];
    }
    float m = m_t;
    #pragma unroll
    for (int o = 16; o > 0; o >>= 1)
        m = fmaxf(m, __shfl_xor_sync(0xffffffffu, m, o));
    if (tid < 64 && lane == 0) red[warp] = m;
    __syncthreads();
    const float M = fmaxf(red[0], red[1]);
    float cc = 0.f;
    if (tid < 64) { cc = __expf(m_t - M); coef[tid] = cc; }
    float zz = z_t * cc;
    #pragma unroll
    for (int o = 16; o > 0; o >>= 1)
        zz += __shfl_xor_sync(0xffffffffu, zz, o);
    if (tid < 64 && lane == 0) red[2 + warp] = zz;
    __syncthreads();
    const float inv = 1.f / (red[2] + red[3]);

    const int col = tid & 63;           // float2 column within slice
    const int tg  = tid >> 6;           // tile group 0..7
    const float2* pa = (const float2*)(g_pacc + (size_t)b * 64 * D_)
                     + (size_t)q * 64 + col;
    float2 a = make_float2(0.f, 0.f);
    #pragma unroll
    for (int t = 0; t < 8; ++t) {
        const int tt = tg * 8 + t;
        const float c = coef[tt];
        const float2 v = pa[(size_t)tt * (D_ / 2)];
        a.x += c * v.x; a.y += c * v.y;
    }
    part[tid] = a;
    __syncthreads();
    if (tid < 64) {
        float2 s = part[tid];
        #pragma unroll
        for (int t = 1; t < 8; ++t) {
            const float2 v = part[t * 64 + tid];
            s.x += v.x; s.y += v.y;
        }
        s.x *= inv; s.y *= inv;
        ((float2*)(out + b * D_))[q * 64 + tid] = s;
    }
}

extern "C" void kernel_launch(void* const* d_in, const int* in_sizes, int n_in,
                              void* d_out, int out_size) {
    const float* x    = (const float*)d_in[0];
    const float* prev = (const float*)d_in[1];
    const float* W1   = (const float*)d_in[2];
    const float* b1   = (const float*)d_in[3];
    const float* w2   = (const float*)d_in[4];
    float* out = (float*)d_out;

    const size_t smem = (size_t)2 * BM * APAD * 2      // Ah
                      + (size_t)2 * BKC * BPADB * 2    // Bs
                      + (size_t)D_ * 4                 // psbuf
                      + (size_t)H_ * 4 * 2             // b1s + w2s
                      + (size_t)BM * 4 * 2             // scoreBuf + pbuf
                      + 4 * 4                          // redsm
                      + (size_t)16 * 320 * 4;          // stage
    cudaFuncSetAttribute(scores_kernel, cudaFuncAttributeMaxDynamicSharedMemorySize, (int)smem);

    convert_w1_kernel<<<128, 256>>>(W1);
    scores_kernel<<<GRIDP, NTHREADS, smem>>>(x, prev, b1, w2);
    finalize_kernel<<<dim3(B_, 8), 512>>>(out);
}